// round 17
// baseline (speedup 1.0000x reference)
#include <cuda_runtime.h>
#include <math.h>

#define BB 64
#define TT 256
#define IND 1024
#define HH 2048
#define MM 512
#define LL 2
#define CK 2560            // H + M
#define SX 8               // K-splits for preact (fb / Wc) -> x partials
#define SXP 6              // K-splits for xp
#define SU 13              // u/r splits: 10 H-part + 3 M-part
#define SUH 10
#define SC 12              // cand splits (all H)
#define NTG 304            // 104 u + 104 r + 96 cand tiles
#define KC 32
#define SPAD 68
#define NBLK_MAX 512

__device__ float g_xpp[3][SXP][BB * HH];  // xp partials, ring over t
__device__ float g_x[SX][BB * HH];        // preact partials (current layer)
__device__ float g_h[LL][BB * MM];        // normalized hidden states
__device__ float g_upart[SU][BB * MM];
__device__ float g_rpart[SU][BB * MM];
__device__ float g_cpart[SC][BB * MM];
__device__ float g_uW[LL * MM * CK];      // upd_W with H-cols folded by ln_w
__device__ float g_rW[LL * MM * CK];
__device__ float g_cW[LL * MM * HH];      // cell_W folded
__device__ float g_Wc[HH * MM];           // sk_W + lc_W
__device__ float g_bc[HH];
__device__ float g_dbase[LL * MM];
__device__ float g_c1[3][LL * MM];        // sum_k ln_w*W  (H part)
__device__ float g_c2[3][LL * MM];        // sum_k ln_b*W + gate bias
__device__ volatile unsigned int g_slot[NBLK_MAX];
__device__ volatile unsigned int g_release;

struct SP {
    const float *x, *W_in, *b_in;
    const float *upd_W, *upd_b, *rst_W, *rst_b, *cell_W, *cell_b;
    const float *fb_W, *fb_b, *ln_w, *ln_b, *mn_w, *mn_b;
    float* out;
};
struct IP {
    const float *hidden, *tau, *lc_W, *lc_b, *sk_W, *sk_b;
    const float *upd_W, *rst_W, *cell_W, *ln_w;
};

// ---- flag-array grid barrier (no same-address atomics) ----
__device__ __forceinline__ void gsync(unsigned int& target, int nblk) {
    __syncthreads();
    target++;
    if (threadIdx.x == 0) { __threadfence(); g_slot[blockIdx.x] = target; }
    if (blockIdx.x == 0) {
        for (int i = threadIdx.x; i < nblk; i += blockDim.x)
            while (g_slot[i] < target) { }
        __syncthreads();
        if (threadIdx.x == 0) { __threadfence(); g_release = target; }
    } else {
        if (threadIdx.x == 0) { while (g_release < target) { } }
    }
    __threadfence();
    __syncthreads();
}

__device__ __forceinline__ float2 block_stats(float s1, float s2, float* red) {
    #pragma unroll
    for (int o = 16; o; o >>= 1) {
        s1 += __shfl_down_sync(0xffffffffu, s1, o);
        s2 += __shfl_down_sync(0xffffffffu, s2, o);
    }
    int w = threadIdx.x >> 5;
    if ((threadIdx.x & 31) == 0) { red[w] = s1; red[8 + w] = s2; }
    __syncthreads();
    if (threadIdx.x == 0) {
        float a = 0.f, b = 0.f;
        #pragma unroll
        for (int i = 0; i < 8; i++) { a += red[i]; b += red[8 + i]; }
        red[16] = a; red[17] = b;
    }
    __syncthreads();
    float2 r = make_float2(red[16], red[17]);
    __syncthreads();
    return r;
}

// ---- packed f32x2 helpers ----
__device__ __forceinline__ unsigned long long dup2(float x) {
    unsigned long long r;
    asm("mov.b64 %0, {%1, %1};" : "=l"(r) : "f"(x));
    return r;
}
__device__ __forceinline__ void fma2(unsigned long long& d,
                                     unsigned long long a, unsigned long long b) {
    asm("fma.rn.f32x2 %0, %1, %2, %0;" : "+l"(d) : "l"(a), "l"(b));
}
__device__ __forceinline__ float2 unpk2(unsigned long long v) {
    float2 r;
    asm("mov.b64 {%0, %1}, %2;" : "=f"(r.x), "=f"(r.y) : "l"(v));
    return r;
}

template<int NP>
__device__ __forceinline__ float4 loadA(const float* p, size_t pstride) {
    float4 a = *(const float4*)p;
    #pragma unroll
    for (int q = 1; q < NP; q++) {
        float4 e = *(const float4*)(p + (size_t)q * pstride);
        a.x += e.x; a.y += e.y; a.z += e.z; a.w += e.w;
    }
    return a;
}

// C[row,col] = scale*(sum_k A[row,k]*W[col,k] + bias[col]) + add2[col] + sum_q xp[q][row,col]
// A summed over NP partials at stride pstride. k0, klen multiples of 32 (klen may be 0).
template<int NP>
__device__ __forceinline__ void gemm_tile(
    const float* __restrict__ A, size_t lda, size_t pstride,
    const float* __restrict__ W, size_t ldw,
    float* __restrict__ C, int ldc,
    int k0, int klen,
    const float* __restrict__ bias, float scale,
    const float* __restrict__ add2, const float* __restrict__ xp,
    float* sA, float* sW)
{
    const int tid = threadIdx.x;
    const int tx = tid & 15, ty = tid >> 4;
    const int kg = (tid & 7) << 2;
    const int lr = tid >> 3;

    unsigned long long acc[4][2];
    #pragma unroll
    for (int i = 0; i < 4; i++) { acc[i][0] = 0ull; acc[i][1] = 0ull; }

    const float* Ag = A + (size_t)lr * lda + k0 + kg;
    const float* Wg = W + (size_t)lr * ldw + k0 + kg;
    float4 qa[2], qw[2];
    qa[0] = loadA<NP>(Ag, pstride);
    qa[1] = loadA<NP>(Ag + (size_t)32 * lda, pstride);
    qw[0] = *(const float4*)Wg;
    qw[1] = *(const float4*)(Wg + (size_t)32 * ldw);

    const int nch = klen >> 5;
    for (int ch = 0; ch < nch; ch++) {
        __syncthreads();
        #pragma unroll
        for (int i = 0; i < 2; i++) {
            int row = lr + (i << 5);
            sA[(kg + 0) * SPAD + row] = qa[i].x;
            sA[(kg + 1) * SPAD + row] = qa[i].y;
            sA[(kg + 2) * SPAD + row] = qa[i].z;
            sA[(kg + 3) * SPAD + row] = qa[i].w;
            sW[(kg + 0) * SPAD + row] = qw[i].x;
            sW[(kg + 1) * SPAD + row] = qw[i].y;
            sW[(kg + 2) * SPAD + row] = qw[i].z;
            sW[(kg + 3) * SPAD + row] = qw[i].w;
        }
        __syncthreads();
        if (ch + 1 < nch) {
            const float* Ag2 = Ag + (size_t)(ch + 1) * KC;
            const float* Wg2 = Wg + (size_t)(ch + 1) * KC;
            qa[0] = loadA<NP>(Ag2, pstride);
            qa[1] = loadA<NP>(Ag2 + (size_t)32 * lda, pstride);
            qw[0] = *(const float4*)Wg2;
            qw[1] = *(const float4*)(Wg2 + (size_t)32 * ldw);
        }
        #pragma unroll
        for (int kk = 0; kk < KC; kk++) {
            float4 a = *(const float4*)(sA + kk * SPAD + (ty << 2));
            ulonglong2 w = *(const ulonglong2*)(sW + kk * SPAD + (tx << 2));
            unsigned long long a0 = dup2(a.x), a1 = dup2(a.y);
            unsigned long long a2 = dup2(a.z), a3 = dup2(a.w);
            fma2(acc[0][0], a0, w.x); fma2(acc[0][1], a0, w.y);
            fma2(acc[1][0], a1, w.x); fma2(acc[1][1], a1, w.y);
            fma2(acc[2][0], a2, w.x); fma2(acc[2][1], a2, w.y);
            fma2(acc[3][0], a3, w.x); fma2(acc[3][1], a3, w.y);
        }
    }

    #pragma unroll
    for (int i = 0; i < 4; i++) {
        float2 c01 = unpk2(acc[i][0]);
        float2 c23 = unpk2(acc[i][1]);
        float4 v = make_float4(c01.x, c01.y, c23.x, c23.y);
        int row = ty * 4 + i;
        if (bias) {
            v.x += bias[tx * 4 + 0]; v.y += bias[tx * 4 + 1];
            v.z += bias[tx * 4 + 2]; v.w += bias[tx * 4 + 3];
        }
        v.x *= scale; v.y *= scale; v.z *= scale; v.w *= scale;
        if (add2) {
            v.x += add2[tx * 4 + 0]; v.y += add2[tx * 4 + 1];
            v.z += add2[tx * 4 + 2]; v.w += add2[tx * 4 + 3];
        }
        if (xp) {
            #pragma unroll
            for (int q = 0; q < SXP; q++) {
                float4 e = *(const float4*)(xp + (size_t)q * (BB * HH) + (size_t)row * HH + tx * 4);
                v.x += e.x; v.y += e.y; v.z += e.z; v.w += e.w;
            }
        }
        *(float4*)(C + (size_t)row * ldc + tx * 4) = v;
    }
}

// ---- init kernels ----
__global__ void init_kernel(IP p) {
    int idx = blockIdx.x * blockDim.x + threadIdx.x;
    int stride = gridDim.x * blockDim.x;
    if (idx == 0) g_release = 0;
    for (int i = idx; i < NBLK_MAX; i += stride) g_slot[i] = 0;
    for (int i = idx; i < HH * MM; i += stride) g_Wc[i] = p.sk_W[i] + p.lc_W[i];
    for (int i = idx; i < HH; i += stride) g_bc[i] = p.sk_b[i] + p.lc_b[i];
    for (int i = idx; i < LL * MM; i += stride) {
        float ta = p.tau[i];
        float sp = (ta > 20.f) ? ta : log1pf(expf(ta));
        sp = fminf(fmaxf(sp, 0.1f), 10.f);
        g_dbase[i] = expf(-1.f / sp);
    }
    for (int i = idx; i < LL * BB * MM; i += stride) ((float*)g_h)[i] = p.hidden[i];
    for (int i = idx; i < LL * MM * CK; i += stride) {
        int l = i / (MM * CK), k = i % CK;
        float f = (k < HH) ? p.ln_w[l * HH + k] : 1.f;
        g_uW[i] = p.upd_W[i] * f;
        g_rW[i] = p.rst_W[i] * f;
    }
    for (int i = idx; i < LL * MM * HH; i += stride) {
        int l = i / (MM * HH), k = i % HH;
        g_cW[i] = p.cell_W[i] * p.ln_w[l * HH + k];
    }
}

__global__ void init2_kernel(SP p) {
    int gwid = (blockIdx.x * blockDim.x + threadIdx.x) >> 5;
    int lane = threadIdx.x & 31;
    if (gwid >= 3 * LL * MM) return;
    int g = gwid / (LL * MM);
    int rem = gwid % (LL * MM);
    int l = rem / MM;
    const float* Wrow;
    const float* bias;
    if (g == 0)      { Wrow = p.upd_W  + (size_t)rem * CK; bias = p.upd_b; }
    else if (g == 1) { Wrow = p.rst_W  + (size_t)rem * CK; bias = p.rst_b; }
    else             { Wrow = p.cell_W + (size_t)rem * HH; bias = p.cell_b; }
    float s1 = 0.f, s2 = 0.f;
    for (int k = lane; k < HH; k += 32) {
        float w = Wrow[k];
        s1 += p.ln_w[l * HH + k] * w;
        s2 += p.ln_b[l * HH + k] * w;
    }
    #pragma unroll
    for (int o = 16; o; o >>= 1) {
        s1 += __shfl_down_sync(0xffffffffu, s1, o);
        s2 += __shfl_down_sync(0xffffffffu, s2, o);
    }
    if (lane == 0) {
        g_c1[g][rem] = s1;
        g_c2[g][rem] = s2 + bias[rem];
    }
}

// ---- scan phases ----
__device__ __noinline__ void preact0(const SP& p, int t, int nblk, float* sA, float* sW) {
    int slot = t % 3;
    bool dofb = (t > 0);
    for (int id = blockIdx.x; id < SX * 32; id += nblk) {
        int s = id >> 5, n0 = (id & 31) * 64;
        gemm_tile<1>(g_h[1], MM, 0,
                     p.fb_W + (size_t)n0 * MM, MM,
                     g_x[s] + n0, HH,
                     s * 64, dofb ? 64 : 0,
                     p.fb_b + n0, dofb ? 0.1f : 0.f,
                     (s == 0) ? p.b_in + n0 : nullptr,
                     (s == 0) ? &g_xpp[slot][0][0] + n0 : nullptr,
                     sA, sW);
    }
}

__device__ __noinline__ void preact1(int nblk, float* sA, float* sW) {
    for (int id = blockIdx.x; id < SX * 32; id += nblk) {
        int s = id >> 5, n0 = (id & 31) * 64;
        gemm_tile<1>(g_h[0], MM, 0,
                     g_Wc + (size_t)n0 * MM, MM,
                     g_x[s] + n0, HH,
                     s * 64, 64,
                     (s == 0) ? g_bc + n0 : nullptr, 1.f,
                     nullptr, nullptr, sA, sW);
    }
}

__device__ __noinline__ void gate_phase(int l, int nblk, float* sA, float* sW) {
    for (int id = blockIdx.x; id < NTG; id += nblk) {
        if (id < 208) {
            const float* Wf = (id < 104) ? g_uW : g_rW;
            float* Cb = (id < 104) ? &g_upart[0][0] : &g_rpart[0][0];
            int jj = id % 104;
            int s = jj >> 3, n0 = (jj & 7) * 64;
            float* C = Cb + (size_t)s * (BB * MM) + n0;
            if (s < SUH) {
                int c0 = (64 * s) / SUH, c1 = (64 * (s + 1)) / SUH;
                gemm_tile<SX>(&g_x[0][0], HH, (size_t)BB * HH,
                              Wf + (size_t)(l * MM + n0) * CK, CK,
                              C, MM, c0 * 32, (c1 - c0) * 32,
                              nullptr, 1.f, nullptr, nullptr, sA, sW);
            } else {
                int s2 = s - SUH;
                int c0 = (16 * s2) / 3, c1 = (16 * (s2 + 1)) / 3;
                gemm_tile<1>(g_h[l], MM, 0,
                             Wf + (size_t)(l * MM + n0) * CK + HH, CK,
                             C, MM, c0 * 32, (c1 - c0) * 32,
                             nullptr, 1.f, nullptr, nullptr, sA, sW);
            }
        } else {
            int jj = id - 208;
            int s = jj >> 3, n0 = (jj & 7) * 64;
            int c0 = (64 * s) / SC, c1 = (64 * (s + 1)) / SC;
            gemm_tile<SX>(&g_x[0][0], HH, (size_t)BB * HH,
                          g_cW + (size_t)(l * MM + n0) * HH, HH,
                          &g_cpart[0][0] + (size_t)s * (BB * MM) + n0, MM,
                          c0 * 32, (c1 - c0) * 32,
                          nullptr, 1.f, nullptr, nullptr, sA, sW);
        }
    }
}

__device__ __noinline__ void pw_phase(const SP& p, int l, int t, float* red) {
    int r = blockIdx.x;
    int tid = threadIdx.x;
    // stats of assembled x row
    float s1 = 0.f, s2 = 0.f;
    for (int j = 0; j < 8; j++) {
        int h = tid + j * 256;
        float v = 0.f;
        #pragma unroll
        for (int s = 0; s < SX; s++) v += g_x[s][r * HH + h];
        s1 += v; s2 += v * v;
    }
    float2 S = block_stats(s1, s2, red);
    float mu = S.x * (1.f / HH);
    float inv = rsqrtf(S.y * (1.f / HH) - mu * mu + 1e-5f);
    float nm = -inv * mu;

    float hv[2];
    float t1 = 0.f, t2 = 0.f;
    #pragma unroll
    for (int j = 0; j < 2; j++) {
        int m = tid + j * 256;
        int idx = l * MM + m;
        int rm = r * MM + m;
        float suH = 0.f, srH = 0.f, suM = 0.f, srM = 0.f, scH = 0.f;
        #pragma unroll
        for (int s = 0; s < SUH; s++) { suH += g_upart[s][rm]; srH += g_rpart[s][rm]; }
        #pragma unroll
        for (int s = SUH; s < SU; s++) { suM += g_upart[s][rm]; srM += g_rpart[s][rm]; }
        #pragma unroll
        for (int s = 0; s < SC; s++) scH += g_cpart[s][rm];
        float u_pre = inv * suH + nm * g_c1[0][idx] + g_c2[0][idx] + suM;
        float r_pre = inv * srH + nm * g_c1[1][idx] + g_c2[1][idx] + srM;
        float c_pre = inv * scH + nm * g_c1[2][idx] + g_c2[2][idx];
        float u  = 1.f / (1.f + expf(-u_pre));
        float rg = 1.f / (1.f + expf(-r_pre));
        float cc = tanhf(c_pre);
        float hold = g_h[l][rm];
        float dec = g_dbase[idx] * u;
        float hn = dec * (hold * rg) + (1.f - dec) * cc;
        hv[j] = hn; t1 += hn; t2 += hn * hn;
    }
    float2 S2 = block_stats(t1, t2, red);
    float mu2 = S2.x * (1.f / MM);
    float inv2 = rsqrtf(S2.y * (1.f / MM) - mu2 * mu2 + 1e-5f);
    #pragma unroll
    for (int j = 0; j < 2; j++) {
        int m = tid + j * 256;
        int idx = l * MM + m;
        int rm = r * MM + m;
        float hnorm = (hv[j] - mu2) * inv2 * p.mn_w[idx] + p.mn_b[idx];
        g_h[l][rm] = hnorm;
        if (l == 1) p.out[(size_t)(r * TT + t) * MM + m] = hnorm;
    }
}

__device__ __noinline__ void xp_run(const SP& p, int t, int half, int nblk,
                                    float* sA, float* sW) {
    int tp = t + 2;
    if (tp >= TT) return;
    for (int id = blockIdx.x - BB; id < 96; id += (nblk - BB)) {
        int g = half * 96 + id;          // 0..191
        int s = g / 32, c = g % 32;
        int c0 = (32 * s) / SXP, c1 = (32 * (s + 1)) / SXP;
        gemm_tile<1>(p.x + (size_t)tp * IND, (size_t)TT * IND, 0,
                     p.W_in + (size_t)(c * 64) * IND, IND,
                     g_xpp[tp % 3][s] + c * 64, HH,
                     c0 * 32, (c1 - c0) * 32,
                     nullptr, 1.f, nullptr, nullptr, sA, sW);
    }
}

__global__ void __launch_bounds__(256, 2) scan_kernel(SP p) {
    __shared__ __align__(16) float sm[2 * KC * SPAD];
    __shared__ float red[18];
    float* sA = sm;
    float* sW = sm + KC * SPAD;
    const int nblk = gridDim.x;
    unsigned int target = 0;

    // prologue: xp for t=0,1 (2 x 192 tiles)
    for (int id = blockIdx.x; id < 2 * 192; id += nblk) {
        int tt = id / 192, g = id % 192;
        int s = g / 32, c = g % 32;
        int c0 = (32 * s) / SXP, c1 = (32 * (s + 1)) / SXP;
        gemm_tile<1>(p.x + (size_t)tt * IND, (size_t)TT * IND, 0,
                     p.W_in + (size_t)(c * 64) * IND, IND,
                     g_xpp[tt][s] + c * 64, HH,
                     c0 * 32, (c1 - c0) * 32,
                     nullptr, 1.f, nullptr, nullptr, sA, sW);
    }
    gsync(target, nblk);

    for (int t = 0; t < TT; t++) {
        preact0(p, t, nblk, sA, sW);
        gsync(target, nblk);
        gate_phase(0, nblk, sA, sW);
        gsync(target, nblk);
        if (blockIdx.x < BB) pw_phase(p, 0, t, red); else xp_run(p, t, 0, nblk, sA, sW);
        gsync(target, nblk);
        preact1(nblk, sA, sW);
        gsync(target, nblk);
        gate_phase(1, nblk, sA, sW);
        gsync(target, nblk);
        if (blockIdx.x < BB) pw_phase(p, 1, t, red); else xp_run(p, t, 1, nblk, sA, sW);
        gsync(target, nblk);
    }

    for (int i = blockIdx.x * 256 + threadIdx.x; i < LL * BB * MM; i += nblk * 256) {
        p.out[(size_t)BB * TT * MM + i] = ((float*)g_h)[i];
    }
}

extern "C" void kernel_launch(void* const* d_in, const int* in_sizes, int n_in,
                              void* d_out, int out_size) {
    (void)in_sizes; (void)n_in; (void)out_size;

    SP sp;
    sp.x      = (const float*)d_in[0];
    sp.W_in   = (const float*)d_in[2];
    sp.b_in   = (const float*)d_in[3];
    sp.cell_W = (const float*)d_in[4];
    sp.cell_b = (const float*)d_in[5];
    sp.upd_W  = (const float*)d_in[6];
    sp.upd_b  = (const float*)d_in[7];
    sp.rst_W  = (const float*)d_in[8];
    sp.rst_b  = (const float*)d_in[9];
    sp.fb_W   = (const float*)d_in[15];
    sp.fb_b   = (const float*)d_in[16];
    sp.ln_w   = (const float*)d_in[17];
    sp.ln_b   = (const float*)d_in[18];
    sp.mn_w   = (const float*)d_in[19];
    sp.mn_b   = (const float*)d_in[20];
    sp.out    = (float*)d_out;

    IP ip;
    ip.hidden = (const float*)d_in[1];
    ip.tau    = (const float*)d_in[10];
    ip.lc_W   = (const float*)d_in[11];
    ip.lc_b   = (const float*)d_in[12];
    ip.sk_W   = (const float*)d_in[13];
    ip.sk_b   = (const float*)d_in[14];
    ip.upd_W  = sp.upd_W;
    ip.rst_W  = sp.rst_W;
    ip.cell_W = sp.cell_W;
    ip.ln_w   = sp.ln_w;

    int dev = 0;
    cudaGetDevice(&dev);
    cudaDeviceProp prop;
    cudaGetDeviceProperties(&prop, dev);
    int occ = 0;
    cudaOccupancyMaxActiveBlocksPerMultiprocessor(&occ, scan_kernel, 256, 0);
    if (occ < 1) occ = 1;
    if (occ > 2) occ = 2;
    int nblk = prop.multiProcessorCount * occ;
    if (nblk > NBLK_MAX) nblk = NBLK_MAX;

    init_kernel<<<512, 256>>>(ip);
    init2_kernel<<<768, 256>>>(sp);
    scan_kernel<<<nblk, 256>>>(sp);
}